// round 17
// baseline (speedup 1.0000x reference)
#include <cuda_runtime.h>
#include <cuda_bf16.h>
#include <math.h>
#include <stdint.h>

#define H 1024
#define L 4096
#define G3 3072
#define NCTA 64     // CTAs per direction in recurrence
#define UNITS 16    // hidden units per CTA
#define NWKR 20     // GEMM worker CTAs (SMs 128..147)
#define NTILE 3072  // total GEMM tiles (48 n * 32 m * 2 dir)

typedef unsigned long long u64;
typedef unsigned int u32;

// Scratch
__device__ float g_Gi[2][L][G3];              // input projections (~100.7 MB)
__device__ unsigned int g_ctr[2 * L];         // per-step arrival counters
__device__ unsigned int g_gi_ready[64];       // [dir*32 + mtile] finished n-tiles
__device__ float g_h[2][2][H];                // [dir][parity][H] h exchange
__device__ __nv_bfloat16 g_xh[L * H], g_xl[L * H];          // x split
__device__ __nv_bfloat16 g_wh[2][G3 * H], g_wl[2][G3 * H];  // Wih split

// ---------------------------------------------------------------------------
// PTX helpers
// ---------------------------------------------------------------------------
__device__ __forceinline__ void ffma2(u64& acc, u64 a, u64 b) {
    asm("fma.rn.f32x2 %0, %1, %2, %3;" : "=l"(acc) : "l"(a), "l"(b), "l"(acc));
}
__device__ __forceinline__ float hsum2(u64 v) {
    float lo, hi;
    asm("mov.b64 {%0, %1}, %2;" : "=f"(lo), "=f"(hi) : "l"(v));
    return lo + hi;
}
__device__ __forceinline__ void arrive_release(unsigned int* p) {
    asm volatile("red.release.gpu.global.add.u32 [%0], 1;" :: "l"(p) : "memory");
}
__device__ __forceinline__ unsigned int ld_acquire(const unsigned int* p) {
    unsigned int v;
    asm volatile("ld.acquire.gpu.global.u32 %0, [%1];" : "=r"(v) : "l"(p) : "memory");
    return v;
}
__device__ __forceinline__ void mma_bf16(float& d0, float& d1, float& d2, float& d3,
                                         u32 a0, u32 a1, u32 a2, u32 a3,
                                         u32 b0, u32 b1) {
    asm("mma.sync.aligned.m16n8k16.row.col.f32.bf16.bf16.f32 "
        "{%0,%1,%2,%3}, {%4,%5,%6,%7}, {%8,%9}, {%0,%1,%2,%3};"
        : "+f"(d0), "+f"(d1), "+f"(d2), "+f"(d3)
        : "r"(a0), "r"(a1), "r"(a2), "r"(a3), "r"(b0), "r"(b1));
}
__device__ __forceinline__ void ldsm_x4(u32& r0, u32& r1, u32& r2, u32& r3, u32 addr) {
    asm volatile("ldmatrix.sync.aligned.m8n8.x4.shared.b16 {%0,%1,%2,%3}, [%4];"
        : "=r"(r0), "=r"(r1), "=r"(r2), "=r"(r3) : "r"(addr));
}
__device__ __forceinline__ void cp16(u32 dst, const void* src) {
    asm volatile("cp.async.cg.shared.global [%0], [%1], 16;" :: "r"(dst), "l"(src));
}

// ---------------------------------------------------------------------------
__global__ void dummy_kernel() {}

__global__ void reset_kernel() {
    int i = blockIdx.x * blockDim.x + threadIdx.x;
    for (int k = i; k < 2 * L; k += gridDim.x * blockDim.x) g_ctr[k] = 0u;
    if (i < 64) g_gi_ready[i] = 0u;
}

// ---------------------------------------------------------------------------
// Split fp32 -> bf16 hi/lo for x, Wf, Wr
// ---------------------------------------------------------------------------
__global__ void conv_kernel(const float* __restrict__ x,
                            const float* __restrict__ Wf,
                            const float* __restrict__ Wr) {
    int i = blockIdx.x * blockDim.x + threadIdx.x;
    int stride = gridDim.x * blockDim.x;
    for (int k = i; k < L * H; k += stride) {
        float f = x[k];
        __nv_bfloat16 hi = __float2bfloat16(f);
        g_xh[k] = hi;
        g_xl[k] = __float2bfloat16(f - __bfloat162float(hi));
    }
    for (int k = i; k < G3 * H; k += stride) {
        float f0 = Wf[k];
        __nv_bfloat16 h0 = __float2bfloat16(f0);
        g_wh[0][k] = h0;
        g_wl[0][k] = __float2bfloat16(f0 - __bfloat162float(h0));
        float f1 = Wr[k];
        __nv_bfloat16 h1 = __float2bfloat16(f1);
        g_wh[1][k] = h1;
        g_wl[1][k] = __float2bfloat16(f1 - __bfloat162float(h1));
    }
}

// ---------------------------------------------------------------------------
// Fused kernel: CTAs 0..127 = GRU recurrence, CTAs 128..147 = GEMM workers.
// ---------------------------------------------------------------------------
__device__ __forceinline__ float sigm(float v) {
    return 1.0f / (1.0f + __expf(-v));
}
__device__ __forceinline__ float tanh_fast(float v) {
    return 2.0f / (1.0f + __expf(-2.0f * v)) - 1.0f;
}

#define SSTR 40
#define A_MAT   10240u   // 128*40*2
#define A_STAGE 20480u
#define B_MAT   5120u    // 64*40*2
#define B_STAGE 10240u
#define B_BASE  40960u
#define DYN_BYTES 61440

__global__ __launch_bounds__(512, 1) void fused_kernel(
    const float* __restrict__ Whh_f, const float* __restrict__ bhh_f,
    const float* __restrict__ Whh_r, const float* __restrict__ bhh_r,
    const float* __restrict__ bih_f, const float* __restrict__ bih_r,
    float* __restrict__ out)
{
    extern __shared__ char dyn[];
    const int bx  = blockIdx.x;
    const int tid = threadIdx.x;

    if (bx >= 2 * NCTA) {
        // ------------------- GEMM worker path -------------------
        const int wkr  = bx - 2 * NCTA;
        const int wid  = tid >> 5, lane = tid & 31;
        const int wm   = wid >> 1, wn = wid & 1;
        const int r0   = lane >> 2, c0 = (lane & 3) * 2;
        const int g    = lane >> 3, rr = lane & 7;

        u32 aoff[2], boff[2];
        #pragma unroll
        for (int mt = 0; mt < 2; ++mt)
            aoff[mt] = (u32)(((wm * 32 + mt * 16 + (g & 1) * 8 + rr) * SSTR
                              + (g >> 1) * 8) * 2);
        #pragma unroll
        for (int p = 0; p < 2; ++p)
            boff[p] = (u32)(((wn * 32 + p * 16 + (g >> 1) * 8 + rr) * SSTR
                              + (g & 1) * 8) * 2);

        const u32 smb = (u32)__cvta_generic_to_shared(dyn);
        const int arow = tid >> 2, aseg = tid & 3;          // A: 512 chunks
        const int brow = (tid & 255) >> 2, bseg = tid & 3;  // B: tid<256

        for (int tile = wkr; tile < NTILE; tile += NWKR) {
            const int level = tile / 96;
            const int j     = tile % 96;
            const int dd    = j & 1;
            const int ntile = j >> 1;
            const int mt    = dd ? (31 - level) : level;
            const int m0    = mt * 128;
            const int n0    = ntile * 64;

            const __nv_bfloat16* __restrict__ xh = g_xh;
            const __nv_bfloat16* __restrict__ xl = g_xl;
            const __nv_bfloat16* __restrict__ wh = g_wh[dd];
            const __nv_bfloat16* __restrict__ wl = g_wl[dd];

            float acc[2][4][4];
            #pragma unroll
            for (int a = 0; a < 2; ++a)
                #pragma unroll
                for (int b = 0; b < 4; ++b)
                    #pragma unroll
                    for (int i = 0; i < 4; ++i) acc[a][b][i] = 0.0f;

            auto load_stage = [&](int ch, int st) {
                const int k0 = ch * 32;
                u32 Ab = smb + st * A_STAGE;
                u32 doff = (u32)(arow * (SSTR * 2) + aseg * 16);
                cp16(Ab + doff,        xh + (size_t)(m0 + arow) * H + k0 + aseg * 8);
                cp16(Ab + A_MAT + doff, xl + (size_t)(m0 + arow) * H + k0 + aseg * 8);
                if (tid < 256) {
                    u32 Bb = smb + B_BASE + st * B_STAGE;
                    u32 db = (u32)(brow * (SSTR * 2) + bseg * 16);
                    cp16(Bb + db,         wh + (size_t)(n0 + brow) * H + k0 + bseg * 8);
                    cp16(Bb + B_MAT + db, wl + (size_t)(n0 + brow) * H + k0 + bseg * 8);
                }
                asm volatile("cp.async.commit_group;");
            };

            load_stage(0, 0);
            for (int ch = 0; ch < H / 32; ++ch) {
                const int st = ch & 1;
                if (ch + 1 < H / 32) {
                    load_stage(ch + 1, st ^ 1);
                    asm volatile("cp.async.wait_group 1;");
                } else {
                    asm volatile("cp.async.wait_group 0;");
                }
                __syncthreads();

                if (wid < 8) {
                    const u32 Ah = smb + st * A_STAGE;
                    const u32 Al = Ah + A_MAT;
                    const u32 Bh = smb + B_BASE + st * B_STAGE;
                    const u32 Bl = Bh + B_MAT;
                    #pragma unroll
                    for (int kk = 0; kk < 32; kk += 16) {
                        const u32 kb = (u32)(kk * 2);
                        u32 ah[2][4], al[2][4], bh[4][2], bl[4][2];
                        #pragma unroll
                        for (int mtt = 0; mtt < 2; ++mtt) {
                            ldsm_x4(ah[mtt][0], ah[mtt][1], ah[mtt][2], ah[mtt][3],
                                    Ah + aoff[mtt] + kb);
                            ldsm_x4(al[mtt][0], al[mtt][1], al[mtt][2], al[mtt][3],
                                    Al + aoff[mtt] + kb);
                        }
                        #pragma unroll
                        for (int p = 0; p < 2; ++p) {
                            ldsm_x4(bh[2*p][0], bh[2*p][1], bh[2*p+1][0], bh[2*p+1][1],
                                    Bh + boff[p] + kb);
                            ldsm_x4(bl[2*p][0], bl[2*p][1], bl[2*p+1][0], bl[2*p+1][1],
                                    Bl + boff[p] + kb);
                        }
                        #pragma unroll
                        for (int mtt = 0; mtt < 2; ++mtt)
                            #pragma unroll
                            for (int nt = 0; nt < 4; ++nt) {
                                float* a = acc[mtt][nt];
                                mma_bf16(a[0], a[1], a[2], a[3],
                                         ah[mtt][0], ah[mtt][1], ah[mtt][2], ah[mtt][3],
                                         bh[nt][0], bh[nt][1]);
                                mma_bf16(a[0], a[1], a[2], a[3],
                                         ah[mtt][0], ah[mtt][1], ah[mtt][2], ah[mtt][3],
                                         bl[nt][0], bl[nt][1]);
                                mma_bf16(a[0], a[1], a[2], a[3],
                                         al[mtt][0], al[mtt][1], al[mtt][2], al[mtt][3],
                                         bh[nt][0], bh[nt][1]);
                            }
                    }
                }
                __syncthreads();
            }

            if (wid < 8) {
                float* __restrict__ C = &g_Gi[dd][0][0];
                const float* __restrict__ bias = dd ? bih_r : bih_f;
                #pragma unroll
                for (int mtt = 0; mtt < 2; ++mtt) {
                    #pragma unroll
                    for (int nt = 0; nt < 4; ++nt) {
                        int row = m0 + wm * 32 + mtt * 16 + r0;
                        int col = n0 + wn * 32 + nt * 8 + c0;
                        float b0v = __ldg(bias + col);
                        float b1v = __ldg(bias + col + 1);
                        float2 o0, o1;
                        o0.x = acc[mtt][nt][0] + b0v; o0.y = acc[mtt][nt][1] + b1v;
                        o1.x = acc[mtt][nt][2] + b0v; o1.y = acc[mtt][nt][3] + b1v;
                        *(float2*)(C + (size_t)row * G3 + col)       = o0;
                        *(float2*)(C + (size_t)(row + 8) * G3 + col) = o1;
                    }
                }
            }
            __syncthreads();
            if (tid == 0) arrive_release(&g_gi_ready[dd * 32 + mt]);
        }
        return;
    }

    // ------------------- GRU recurrence path (golden R2) -------------------
    const int d   = (bx >= NCTA) ? 1 : 0;
    const int cta = d ? bx - NCTA : bx;
    const int u0  = cta * UNITS;
    const int w   = tid >> 5;
    const int l   = tid & 31;
    const int u   = u0 + w;

    const float* __restrict__ Whh = d ? Whh_r : Whh_f;
    const float* __restrict__ bhh = d ? bhh_r : bhh_f;
    const float* __restrict__ Gi  = &g_Gi[d][0][0];
    unsigned int* ctr = g_ctr + d * L;
    float* hbuf0 = &g_h[d][0][0];
    float* hbuf1 = &g_h[d][1][0];

    float* h_s = (float*)dyn;          // 4 KB of the dynamic smem
    const u64* hs64 = (const u64*)h_s;

    u64 w0[16], w1[16], w2[16];
    {
        const u64* r0 = (const u64*)(Whh + (size_t)(u         ) * H + 4 * l);
        const u64* r1 = (const u64*)(Whh + (size_t)(u + H     ) * H + 4 * l);
        const u64* r2 = (const u64*)(Whh + (size_t)(u + 2 * H ) * H + 4 * l);
        #pragma unroll
        for (int c = 0; c < 8; ++c) {
            w0[2*c] = r0[c*64]; w0[2*c+1] = r0[c*64+1];
            w1[2*c] = r1[c*64]; w1[2*c+1] = r1[c*64+1];
            w2[2*c] = r2[c*64]; w2[2*c+1] = r2[c*64+1];
        }
    }
    const float b_r = bhh[u];
    const float b_z = bhh[u + H];
    const float b_n = bhh[u + 2 * H];

    for (int s = 0; s < L; ++s) {
        const int t = d ? (L - 1 - s) : s;

        // Every 128 steps: wait for this block's Gi tiles to be produced.
        if ((s & 127) == 0) {
            const int mt = d ? (31 - (s >> 7)) : (s >> 7);
            if (tid == 0) {
                while (ld_acquire(&g_gi_ready[d * 32 + mt]) < 48u) { }
            }
            __syncthreads();
        }

        float gi_r = 0.f, gi_z = 0.f, gi_n = 0.f;
        if (l == 0) {
            const float* g = Gi + (size_t)t * G3;
            gi_r = __ldg(g + u);
            gi_z = __ldg(g + u + H);
            gi_n = __ldg(g + u + 2 * H);
        }

        if (s == 0) {
            if (tid < 256) ((float4*)h_s)[tid] = make_float4(0.f, 0.f, 0.f, 0.f);
        } else {
            if (tid == 0) {
                while (ld_acquire(&ctr[s - 1]) < (unsigned)NCTA) { }
            }
            __syncthreads();
            const float4* src = (const float4*)(((s - 1) & 1) ? hbuf1 : hbuf0);
            if (tid < 256) ((float4*)h_s)[tid] = __ldcg(src + tid);
        }
        __syncthreads();

        u64 a0 = 0ull, a1 = 0ull, a2 = 0ull;
        #pragma unroll
        for (int c = 0; c < 8; ++c) {
            u64 h0 = hs64[c * 64 + 2 * l];
            u64 h1 = hs64[c * 64 + 2 * l + 1];
            ffma2(a0, w0[2*c], h0); ffma2(a0, w0[2*c+1], h1);
            ffma2(a1, w1[2*c], h0); ffma2(a1, w1[2*c+1], h1);
            ffma2(a2, w2[2*c], h0); ffma2(a2, w2[2*c+1], h1);
        }
        float s0 = hsum2(a0), s1 = hsum2(a1), s2 = hsum2(a2);
        #pragma unroll
        for (int o = 16; o > 0; o >>= 1) {
            s0 += __shfl_xor_sync(0xffffffffu, s0, o);
            s1 += __shfl_xor_sync(0xffffffffu, s1, o);
            s2 += __shfl_xor_sync(0xffffffffu, s2, o);
        }

        if (l == 0) {
            float r  = sigm(gi_r + s0 + b_r);
            float z  = sigm(gi_z + s1 + b_z);
            float n  = tanh_fast(gi_n + r * (s2 + b_n));
            float hp = h_s[u];
            float hn = fmaf(z, hp - n, n);   // (1-z)*n + z*hp
            __stcg(((s & 1) ? hbuf1 : hbuf0) + u, hn);
            out[(size_t)t * (2 * H) + d * H + u] = hn;
            if (s == L - 1) {
                const size_t hid_off = (size_t)L * (2 * H);
                out[hid_off + d * H + u]         = hn;
                out[hid_off + 2 * H + d * H + u] = hn;
            }
        }

        __syncthreads();
        if (tid == 0) arrive_release(&ctr[s]);
    }
}

// ---------------------------------------------------------------------------
// Launch
// ---------------------------------------------------------------------------
extern "C" void kernel_launch(void* const* d_in, const int* in_sizes, int n_in,
                              void* d_out, int out_size)
{
    const float* x    = (const float*)d_in[0];
    const float* fWih = (const float*)d_in[1];
    const float* fWhh = (const float*)d_in[2];
    const float* fbih = (const float*)d_in[3];
    const float* fbhh = (const float*)d_in[4];
    const float* rWih = (const float*)d_in[5];
    const float* rWhh = (const float*)d_in[6];
    const float* rbih = (const float*)d_in[7];
    const float* rbhh = (const float*)d_in[8];
    float* out = (float*)d_out;

    static bool attr_set = false;
    if (!attr_set) {
        cudaFuncSetAttribute(fused_kernel,
                             cudaFuncAttributeMaxDynamicSharedMemorySize, DYN_BYTES);
        attr_set = true;
    }

    dummy_kernel<<<1, 32>>>();
    reset_kernel<<<8, 256>>>();
    conv_kernel<<<1024, 256>>>(x, fWih, rWih);

    fused_kernel<<<2 * NCTA + NWKR, 512, DYN_BYTES>>>(
        fWhh, fbhh, rWhh, rbhh, fbih, rbih, out);
}